// round 3
// baseline (speedup 1.0000x reference)
#include <cuda_runtime.h>

// The reference's second einsum ('bhtl,bthd->bhtd') sums the softmax over l
// alone (rows sum to 1), so ctx[b,h,t,d] == v[b,t,h,d]. The whole model is:
//   out = perm(x @ Wv) @ Wo^T
// with perm = the no-transpose head reshape:
//   Vperm[b, h*128 + t/16, (t%16)*64 + d] = V[b, t, h*64 + d]
// Q/K/mask/softmax are numerically dead code.
//
// Two fp32 SGEMMs (8192x1024x1024 each) using packed fma.rn.f32x2.

#define Mdim 8192
#define Ndim 1024
#define Kdim 1024
#define BM 128
#define BN 128
#define BK 16

// scratch for permuted V (allocation-free rule: device global), 32 MiB
__device__ float g_V[Mdim * Ndim];

typedef unsigned long long u64;

// ---------------------------------------------------------------------------
// Warp-tiled SGEMM with packed f32x2 FMA.
// Block 256 threads = 8 warps (4 along M x 2 along N), warp tile 32x64,
// thread tile 4 rows x 16 cols (8 float2 accumulators per row-pair group).
// BT=0: B is [K,N] row-major (C = A@B). BT=1: B is [N,K] (C = A@B^T).
// PERM=1: epilogue stores through the head-scramble permutation.
// ---------------------------------------------------------------------------
template <int BT, int PERM>
__global__ __launch_bounds__(256, 2) void gemm_f32x2_kernel(
    const float* __restrict__ A, const float* __restrict__ B,
    float* __restrict__ C)
{
    __shared__ float2 As2[BK][BM + 2];  // duplicated pairs (v,v); stride 130
    __shared__ float  Bs[BK][BN];

    const int tid  = threadIdx.x;
    const int warp = tid >> 5;
    const int lane = tid & 31;
    const int wm = warp & 3;        // 0..3 along M
    const int wn = warp >> 2;       // 0..1 along N
    const int rp = lane >> 2;       // 0..7
    const int cp = lane & 3;        // 0..3
    const int row0 = wm * 32 + rp * 4;   // thread's first row in tile
    const int col0 = wn * 64 + cp * 8;   // thread's first col (and col0+32)
    const int brow = blockIdx.y * BM;
    const int bcol = blockIdx.x * BN;

    u64 acc[4][8];  // [row][col-pair]; pairs 0..3 -> cols col0+0..7,
                    //                  pairs 4..7 -> cols col0+32..39
#pragma unroll
    for (int i = 0; i < 4; i++)
#pragma unroll
        for (int j = 0; j < 8; j++) acc[i][j] = 0ull;

    for (int kb = 0; kb < Kdim; kb += BK) {
        // ---- A tile: 128 rows x 16 k, duplicated float2, transposed ----
#pragma unroll
        for (int it = 0; it < 2; it++) {
            int f = tid + it * 256;
            int r = f >> 2;
            int c = (f & 3) << 2;
            float4 v = *(const float4*)(A + (size_t)(brow + r) * Kdim + kb + c);
            As2[c + 0][r] = make_float2(v.x, v.x);
            As2[c + 1][r] = make_float2(v.y, v.y);
            As2[c + 2][r] = make_float2(v.z, v.z);
            As2[c + 3][r] = make_float2(v.w, v.w);
        }
        // ---- B tile ----
        if (BT == 0) {
#pragma unroll
            for (int it = 0; it < 2; it++) {
                int f = tid + it * 256;
                int r = f >> 5;
                int c = (f & 31) << 2;
                *(float4*)(&Bs[r][c]) =
                    *(const float4*)(B + (size_t)(kb + r) * Ndim + bcol + c);
            }
        } else {
#pragma unroll
            for (int it = 0; it < 2; it++) {
                int f = tid + it * 256;
                int n = f >> 2;
                int c = (f & 3) << 2;
                float4 v = *(const float4*)(B + (size_t)(bcol + n) * Kdim + kb + c);
                Bs[c + 0][n] = v.x;
                Bs[c + 1][n] = v.y;
                Bs[c + 2][n] = v.z;
                Bs[c + 3][n] = v.w;
            }
        }
        __syncthreads();

        // ---- compute ----
#pragma unroll
        for (int k = 0; k < BK; k++) {
            u64 a2[4], b2[8];
#pragma unroll
            for (int j = 0; j < 4; j++)
                a2[j] = *(const u64*)&As2[k][row0 + j];
#pragma unroll
            for (int j = 0; j < 4; j++) {
                b2[j]     = *(const u64*)&Bs[k][col0 + 2 * j];
                b2[4 + j] = *(const u64*)&Bs[k][col0 + 32 + 2 * j];
            }
#pragma unroll
            for (int i = 0; i < 4; i++)
#pragma unroll
                for (int j = 0; j < 8; j++)
                    asm("fma.rn.f32x2 %0, %1, %2, %0;"
                        : "+l"(acc[i][j]) : "l"(a2[i]), "l"(b2[j]));
        }
        __syncthreads();
    }

    // ---- epilogue ----
#pragma unroll
    for (int i = 0; i < 4; i++) {
        const int rowg = brow + row0 + i;
#pragma unroll
        for (int g = 0; g < 2; g++) {
            const int n0 = bcol + col0 + g * 32;   // multiple of 8
            float2 p0 = *(float2*)&acc[i][g * 4 + 0];
            float2 p1 = *(float2*)&acc[i][g * 4 + 1];
            float2 p2 = *(float2*)&acc[i][g * 4 + 2];
            float2 p3 = *(float2*)&acc[i][g * 4 + 3];
            float4 v0 = make_float4(p0.x, p0.y, p1.x, p1.y);
            float4 v1 = make_float4(p2.x, p2.y, p3.x, p3.y);
            float* dst;
            if (PERM) {
                // rowg = b*2048 + t ; n0 = h*64 + d (8-col group within one h)
                int b = rowg >> 11;
                int t = rowg & 2047;
                int h = n0 >> 6;
                int d = n0 & 63;
                int prow = b * 2048 + h * 128 + (t >> 4);
                int pcol = ((t & 15) << 6) + d;
                dst = C + (size_t)prow * Ndim + pcol;
            } else {
                dst = C + (size_t)rowg * Ndim + n0;
            }
            *(float4*)dst = v0;
            *(float4*)(dst + 4) = v1;
        }
    }
}

// ---------------------------------------------------------------------------
extern "C" void kernel_launch(void* const* d_in, const int* in_sizes, int n_in,
                              void* d_out, int out_size)
{
    // Expected insertion order: x, mask, Wq, Wk, Wv, Wo_w.
    // Hedge: x is uniquely sized (8388608). If it's not slot 0, assume
    // alphabetical order (Wk, Wo_w, Wq, Wv, mask, x).
    const float* x;
    const float* Wv;
    const float* Wo;
    if (in_sizes[0] == Mdim * Kdim) {           // insertion order
        x  = (const float*)d_in[0];
        Wv = (const float*)d_in[4];
        Wo = (const float*)d_in[5];
    } else {                                     // alphabetical fallback
        x  = (const float*)d_in[5];
        Wv = (const float*)d_in[3];
        Wo = (const float*)d_in[1];
    }
    float* out = (float*)d_out;

    float* Vp;
    cudaGetSymbolAddress((void**)&Vp, g_V);

    dim3 grid(Ndim / BN, Mdim / BM);  // (8, 64)

    // Vperm = perm(x @ Wv)   (permutation fused into the store)
    gemm_f32x2_kernel<0, 1><<<grid, 256>>>(x, Wv, Vp);
    // out = Vperm @ Wo^T
    gemm_f32x2_kernel<1, 0><<<grid, 256>>>(Vp, Wo, out);
}

// round 6
// speedup vs baseline: 1.7184x; 1.7184x over previous
#include <cuda_runtime.h>
#include <cuda_bf16.h>
#include <cstdint>

// out = perm(x @ Wv) @ Wo^T  (reference attention is numerically dead:
// softmax rows sum to 1, einsum 'bhtl,bthd->bhtd' contracts l over A alone).
//
// tcgen05 is unreachable (harness PTX targets compute_103, not 103a), so both
// GEMMs use warp-level mma.sync bf16 (HMMA fallback) with a 3-term split:
//   a = a0 + a1 (bf16 hi + residual),  D = a0b0 + a0b1 + a1b0  -> ~2e-5 error.

#define Mdim 8192
#define Ndim 1024
#define Kdim 1024
typedef __nv_bfloat16 bf16;

// ---- device scratch (allocation-free rule) ----
__device__ bf16 g_x0[Mdim * Kdim];
__device__ bf16 g_x1[Mdim * Kdim];
__device__ bf16 g_wvT0[Ndim * Kdim];
__device__ bf16 g_wvT1[Ndim * Kdim];
__device__ bf16 g_wo0[Ndim * Kdim];
__device__ bf16 g_wo1[Ndim * Kdim];
__device__ bf16 g_v0[Mdim * Kdim];
__device__ bf16 g_v1[Mdim * Kdim];

__device__ __forceinline__ uint32_t smem_u32(const void* p) {
    uint32_t a;
    asm("{ .reg .u64 t; cvta.to.shared.u64 t, %1; cvt.u32.u64 %0, t; }"
        : "=r"(a) : "l"(p));
    return a;
}

#define CP16(dst, src)                                                         \
    asm volatile("cp.async.cg.shared.global [%0], [%1], 16;" ::                \
                 "r"(dst), "l"(src))
#define CP_COMMIT() asm volatile("cp.async.commit_group;")
#define CP_WAIT1()  asm volatile("cp.async.wait_group 1;")
#define CP_WAIT0()  asm volatile("cp.async.wait_group 0;")

#define LDSM_X4(r0, r1, r2, r3, addr)                                          \
    asm volatile("ldmatrix.sync.aligned.m8n8.x4.shared.b16 {%0,%1,%2,%3}, [%4];" \
                 : "=r"(r0), "=r"(r1), "=r"(r2), "=r"(r3) : "r"(addr))
#define LDSM_X2(r0, r1, addr)                                                  \
    asm volatile("ldmatrix.sync.aligned.m8n8.x2.shared.b16 {%0,%1}, [%2];"     \
                 : "=r"(r0), "=r"(r1) : "r"(addr))

#define MMA(d, a, b)                                                           \
    asm volatile("mma.sync.aligned.m16n8k16.row.col.f32.bf16.bf16.f32 "        \
                 "{%0,%1,%2,%3}, {%4,%5,%6,%7}, {%8,%9}, {%0,%1,%2,%3};"       \
                 : "+f"((d)[0]), "+f"((d)[1]), "+f"((d)[2]), "+f"((d)[3])      \
                 : "r"((a)[0]), "r"((a)[1]), "r"((a)[2]), "r"((a)[3]),         \
                   "r"((b)[0]), "r"((b)[1]))

// ---------------- split kernels -------------------------------------------
__global__ void split2_kernel(const float* __restrict__ in,
                              bf16* __restrict__ o0, bf16* __restrict__ o1, int n4)
{
    int i = blockIdx.x * blockDim.x + threadIdx.x;
    if (i >= n4) return;
    float4 v = ((const float4*)in)[i];
    bf16 h0 = __float2bfloat16(v.x), h1 = __float2bfloat16(v.y);
    bf16 h2 = __float2bfloat16(v.z), h3 = __float2bfloat16(v.w);
    bf16 l0 = __float2bfloat16(v.x - __bfloat162float(h0));
    bf16 l1 = __float2bfloat16(v.y - __bfloat162float(h1));
    bf16 l2 = __float2bfloat16(v.z - __bfloat162float(h2));
    bf16 l3 = __float2bfloat16(v.w - __bfloat162float(h3));
    __nv_bfloat162 a = make_bfloat162(h0, h1), b = make_bfloat162(h2, h3);
    __nv_bfloat162 c = make_bfloat162(l0, l1), d = make_bfloat162(l2, l3);
    ((uint2*)o0)[i] = make_uint2(*(uint32_t*)&a, *(uint32_t*)&b);
    ((uint2*)o1)[i] = make_uint2(*(uint32_t*)&c, *(uint32_t*)&d);
}

__global__ void splitT_kernel(const float* __restrict__ in,
                              bf16* __restrict__ o0, bf16* __restrict__ o1)
{
    int id = blockIdx.x * blockDim.x + threadIdx.x;  // 0..1M-1
    int n = id >> 10, k = id & 1023;
    float a = in[k * 1024 + n];
    bf16 h = __float2bfloat16(a);
    o0[id] = h;
    o1[id] = __float2bfloat16(a - __bfloat162float(h));
}

// ---------------- bf16x3 HMMA GEMM ----------------------------------------
// Block 128x128, BK=32, 8 warps (2 M x 4 N), warp tile 64x32.
// D[m,n] = sum_k A[m,k]*B[n,k]; B [n][k] row-major == mma ".col" operand.
// Double-buffered cp.async. PERM=1: GEMM1 epilogue writes bf16 hi/lo splits
// through the head-scramble permutation; PERM=0 writes fp32.
#define LDA 40                       // padded row, bf16 elems (80 B)
#define TILE_B (128 * LDA * 2)       // 10240 B
#define STAGE_B (4 * TILE_B)         // 40960 B
#define SMEM_DYN (2 * STAGE_B)       // 81920 B

#define LOAD_STAGE(sb, kb)                                                     \
    do {                                                                       \
        _Pragma("unroll")                                                      \
        for (int _i = 0; _i < 2; _i++) {                                       \
            int f = tid + _i * 256;                                            \
            int r = f >> 2, c = f & 3;                                         \
            uint32_t so = (sb) + r * (LDA * 2) + c * 16;                       \
            CP16(so,              pA0 + (size_t)r * Kdim + (kb) + c * 8);      \
            CP16(so + TILE_B,     pA1 + (size_t)r * Kdim + (kb) + c * 8);      \
            CP16(so + 2 * TILE_B, pB0 + (size_t)r * Kdim + (kb) + c * 8);      \
            CP16(so + 3 * TILE_B, pB1 + (size_t)r * Kdim + (kb) + c * 8);      \
        }                                                                      \
        CP_COMMIT();                                                           \
    } while (0)

template <int PERM>
__global__ __launch_bounds__(256) void hmma_gemm(
    const bf16* __restrict__ A0g, const bf16* __restrict__ A1g,
    const bf16* __restrict__ B0g, const bf16* __restrict__ B1g,
    float* __restrict__ Cf, bf16* __restrict__ C0, bf16* __restrict__ C1)
{
    extern __shared__ char sm[];
    const int tid = threadIdx.x;
    const int lane = tid & 31;
    const int wid = tid >> 5;
    const int wm = wid & 1;       // 0..1 (64 rows each)
    const int wn = wid >> 1;      // 0..3 (32 cols each)
    const int brow = blockIdx.y * 128;
    const int bcol = blockIdx.x * 128;
    const uint32_t sbase = smem_u32(sm);

    const bf16* pA0 = A0g + (size_t)brow * Kdim;
    const bf16* pA1 = A1g + (size_t)brow * Kdim;
    const bf16* pB0 = B0g + (size_t)bcol * Kdim;
    const bf16* pB1 = B1g + (size_t)bcol * Kdim;

    float acc[4][4][4];
#pragma unroll
    for (int i = 0; i < 4; i++)
#pragma unroll
        for (int j = 0; j < 4; j++)
#pragma unroll
            for (int q = 0; q < 4; q++) acc[i][j][q] = 0.f;

    // ldmatrix lane addressing (byte offsets within a tile)
    const uint32_t a_off = (uint32_t)((wm * 64 + (lane & 15)) * (LDA * 2) +
                                      (lane >> 4) * 16);
    const uint32_t b_off = (uint32_t)((wn * 32 + (lane & 7)) * (LDA * 2) +
                                      ((lane >> 3) & 1) * 16);

    LOAD_STAGE(sbase, 0);   // prologue: stage 0

    for (int it = 0; it < Kdim / 32; it++) {
        if (it + 1 < Kdim / 32) {
            LOAD_STAGE(sbase + ((it + 1) & 1) * STAGE_B, (it + 1) * 32);
            CP_WAIT1();
        } else {
            CP_WAIT0();
        }
        __syncthreads();

        const uint32_t st = sbase + (it & 1) * STAGE_B;
#pragma unroll
        for (int ks = 0; ks < 2; ks++) {
            const uint32_t kso = ks * 32;  // 16 bf16 = 32 B
            uint32_t a0[4][4], a1[4][4], b0[4][2], b1[4][2];
#pragma unroll
            for (int mt = 0; mt < 4; mt++) {
                uint32_t ad = st + a_off + mt * 16 * (LDA * 2) + kso;
                LDSM_X4(a0[mt][0], a0[mt][1], a0[mt][2], a0[mt][3], ad);
                LDSM_X4(a1[mt][0], a1[mt][1], a1[mt][2], a1[mt][3], ad + TILE_B);
            }
#pragma unroll
            for (int nt = 0; nt < 4; nt++) {
                uint32_t bd = st + b_off + nt * 8 * (LDA * 2) + kso;
                LDSM_X2(b0[nt][0], b0[nt][1], bd + 2 * TILE_B);
                LDSM_X2(b1[nt][0], b1[nt][1], bd + 3 * TILE_B);
            }
#pragma unroll
            for (int mt = 0; mt < 4; mt++)
#pragma unroll
                for (int nt = 0; nt < 4; nt++) {
                    MMA(acc[mt][nt], a0[mt], b0[nt]);
                    MMA(acc[mt][nt], a0[mt], b1[nt]);
                    MMA(acc[mt][nt], a1[mt], b0[nt]);
                }
        }
        __syncthreads();
    }

    // ---- epilogue ----
#pragma unroll
    for (int mt = 0; mt < 4; mt++) {
#pragma unroll
        for (int nt = 0; nt < 4; nt++) {
            int m = brow + wm * 64 + mt * 16 + (lane >> 2);
            int n = bcol + wn * 32 + nt * 8 + (lane & 3) * 2;
#pragma unroll
            for (int half = 0; half < 2; half++) {
                int mm = m + half * 8;
                float f0 = acc[mt][nt][2 * half];
                float f1 = acc[mt][nt][2 * half + 1];
                if (PERM) {
                    // mm = b*2048 + t ; n = h*64 + d (pair within one head)
                    int bb = mm >> 11, t = mm & 2047, h = n >> 6;
                    int prow = (bb << 11) + (h << 7) + (t >> 4);
                    int pcol = ((t & 15) << 6) + (n & 63);
                    size_t idx = (size_t)prow * Ndim + pcol;
                    bf16 h0 = __float2bfloat16(f0), h1 = __float2bfloat16(f1);
                    bf16 l0 = __float2bfloat16(f0 - __bfloat162float(h0));
                    bf16 l1 = __float2bfloat16(f1 - __bfloat162float(h1));
                    __nv_bfloat162 ph = make_bfloat162(h0, h1);
                    __nv_bfloat162 pl = make_bfloat162(l0, l1);
                    *(uint32_t*)(C0 + idx) = *(uint32_t*)&ph;
                    *(uint32_t*)(C1 + idx) = *(uint32_t*)&pl;
                } else {
                    *(float2*)(Cf + (size_t)mm * Ndim + n) = make_float2(f0, f1);
                }
            }
        }
    }
}

// ---------------------------------------------------------------------------
extern "C" void kernel_launch(void* const* d_in, const int* in_sizes, int n_in,
                              void* d_out, int out_size)
{
    const float *x, *Wv, *Wo;
    if (in_sizes[0] == Mdim * Kdim) {            // insertion order: x,mask,Wq,Wk,Wv,Wo
        x = (const float*)d_in[0];
        Wv = (const float*)d_in[4];
        Wo = (const float*)d_in[5];
    } else {                                      // alphabetical fallback
        x = (const float*)d_in[5];
        Wv = (const float*)d_in[3];
        Wo = (const float*)d_in[1];
    }
    float* out = (float*)d_out;

    bf16 *x0, *x1, *wvT0, *wvT1, *wo0, *wo1, *v0, *v1;
    cudaGetSymbolAddress((void**)&x0, g_x0);
    cudaGetSymbolAddress((void**)&x1, g_x1);
    cudaGetSymbolAddress((void**)&wvT0, g_wvT0);
    cudaGetSymbolAddress((void**)&wvT1, g_wvT1);
    cudaGetSymbolAddress((void**)&wo0, g_wo0);
    cudaGetSymbolAddress((void**)&wo1, g_wo1);
    cudaGetSymbolAddress((void**)&v0, g_v0);
    cudaGetSymbolAddress((void**)&v1, g_v1);

    cudaFuncSetAttribute(hmma_gemm<1>, cudaFuncAttributeMaxDynamicSharedMemorySize, SMEM_DYN);
    cudaFuncSetAttribute(hmma_gemm<0>, cudaFuncAttributeMaxDynamicSharedMemorySize, SMEM_DYN);

    split2_kernel<<<(Mdim * Kdim / 4 + 255) / 256, 256>>>(x, x0, x1, Mdim * Kdim / 4);
    splitT_kernel<<<(Ndim * Kdim) / 256, 256>>>(Wv, wvT0, wvT1);
    split2_kernel<<<(Ndim * Kdim / 4 + 255) / 256, 256>>>(Wo, wo0, wo1, Ndim * Kdim / 4);

    dim3 grid(Ndim / 128, Mdim / 128);  // (8, 64)
    hmma_gemm<1><<<grid, 256, SMEM_DYN>>>(x0, x1, wvT0, wvT1, nullptr, v0, v1);
    hmma_gemm<0><<<grid, 256, SMEM_DYN>>>(v0, v1, wo0, wo1, out, nullptr, nullptr);
}

// round 10
// speedup vs baseline: 3.2213x; 1.8746x over previous
#include <cuda_runtime.h>
#include <cuda_fp16.h>
#include <cstdint>

// out = perm(x @ Wv) @ Wo^T  (reference attention is numerically dead:
// softmax rows sum to 1, einsum 'bhtl,bthd->bhtd' contracts l over A alone).
//
// fp16 HMMA (mma.sync m16n8k16) with A 2-way split, B single fp16:
//   D = a0*b + a1*b  (exact in A; error = B fp16 quantization ~2e-4 << 1e-3)
// 3-stage cp.async pipeline, one barrier per K-iteration.

#define Mdim 8192
#define Ndim 1024
#define Kdim 1024
typedef __half h16;

// ---- device scratch (allocation-free rule) ----
__device__ h16 g_x0[Mdim * Kdim];
__device__ h16 g_x1[Mdim * Kdim];
__device__ h16 g_wvT[Ndim * Kdim];
__device__ h16 g_wo[Ndim * Kdim];
__device__ h16 g_v0[Mdim * Kdim];
__device__ h16 g_v1[Mdim * Kdim];

__device__ __forceinline__ uint32_t smem_u32(const void* p) {
    uint32_t a;
    asm("{ .reg .u64 t; cvta.to.shared.u64 t, %1; cvt.u32.u64 %0, t; }"
        : "=r"(a) : "l"(p));
    return a;
}

#define CP16(dst, src)                                                         \
    asm volatile("cp.async.cg.shared.global [%0], [%1], 16;" ::                \
                 "r"(dst), "l"(src))
#define CP_COMMIT() asm volatile("cp.async.commit_group;")
#define CP_WAIT1()  asm volatile("cp.async.wait_group 1;")
#define CP_WAIT0()  asm volatile("cp.async.wait_group 0;")

#define LDSM_X4(r0, r1, r2, r3, addr)                                          \
    asm volatile("ldmatrix.sync.aligned.m8n8.x4.shared.b16 {%0,%1,%2,%3}, [%4];" \
                 : "=r"(r0), "=r"(r1), "=r"(r2), "=r"(r3) : "r"(addr))

#define MMA(d, a, b)                                                           \
    asm volatile("mma.sync.aligned.m16n8k16.row.col.f32.f16.f16.f32 "          \
                 "{%0,%1,%2,%3}, {%4,%5,%6,%7}, {%8,%9}, {%0,%1,%2,%3};"       \
                 : "+f"((d)[0]), "+f"((d)[1]), "+f"((d)[2]), "+f"((d)[3])      \
                 : "r"((a)[0]), "r"((a)[1]), "r"((a)[2]), "r"((a)[3]),         \
                   "r"((b)[0]), "r"((b)[1]))

// ---------------- conversion kernels --------------------------------------
__global__ void split_x_kernel(const float* __restrict__ in,
                               h16* __restrict__ o0, h16* __restrict__ o1, int n4)
{
    int i = blockIdx.x * blockDim.x + threadIdx.x;
    if (i >= n4) return;
    float4 v = ((const float4*)in)[i];
    h16 h0 = __float2half_rn(v.x), h1 = __float2half_rn(v.y);
    h16 h2 = __float2half_rn(v.z), h3 = __float2half_rn(v.w);
    h16 l0 = __float2half_rn(v.x - __half2float(h0));
    h16 l1 = __float2half_rn(v.y - __half2float(h1));
    h16 l2 = __float2half_rn(v.z - __half2float(h2));
    h16 l3 = __float2half_rn(v.w - __half2float(h3));
    __half2 a = __halves2half2(h0, h1), b = __halves2half2(h2, h3);
    __half2 c = __halves2half2(l0, l1), d = __halves2half2(l2, l3);
    ((uint2*)o0)[i] = make_uint2(*(uint32_t*)&a, *(uint32_t*)&b);
    ((uint2*)o1)[i] = make_uint2(*(uint32_t*)&c, *(uint32_t*)&d);
}

// Wv [k][n] -> fp16 [n][k] via 32x32 smem tiles (coalesced both sides)
__global__ void convT_kernel(const float* __restrict__ in, h16* __restrict__ o)
{
    __shared__ float t[32][33];
    int k0 = blockIdx.x * 32, n0 = blockIdx.y * 32;
    int tx = threadIdx.x, ty = threadIdx.y;
    for (int j = ty; j < 32; j += 8)
        t[j][tx] = in[(size_t)(k0 + j) * Ndim + n0 + tx];
    __syncthreads();
    for (int j = ty; j < 32; j += 8)
        o[(size_t)(n0 + j) * Kdim + k0 + tx] = __float2half_rn(t[tx][j]);
}

__global__ void conv_kernel(const float* __restrict__ in, h16* __restrict__ o, int n4)
{
    int i = blockIdx.x * blockDim.x + threadIdx.x;
    if (i >= n4) return;
    float4 v = ((const float4*)in)[i];
    __half2 a = __halves2half2(__float2half_rn(v.x), __float2half_rn(v.y));
    __half2 b = __halves2half2(__float2half_rn(v.z), __float2half_rn(v.w));
    ((uint2*)o)[i] = make_uint2(*(uint32_t*)&a, *(uint32_t*)&b);
}

// ---------------- fp16 2-term HMMA GEMM ------------------------------------
// Block 128x128, BK=32, 8 warps (2 M x 4 N), warp tile 64x32.
// D[m,n] = sum_k A[m,k]*B[n,k]; B [n][k] row-major == mma ".col" operand.
// 3-stage cp.async ring, ONE __syncthreads per iteration.
#define PITCH 80                     // padded row bytes (32 fp16 = 64B data)
#define TILE_B (128 * PITCH)         // 10240
#define STAGE_B (3 * TILE_B)         // 30720 (a0, a1, b)
#define SMEM_DYN (3 * STAGE_B)       // 92160
#define NIT (Kdim / 32)              // 32

#define LOAD_STAGE(sb, kb)                                                     \
    do {                                                                       \
        _Pragma("unroll")                                                      \
        for (int _i = 0; _i < 2; _i++) {                                       \
            int _f = tid + _i * 256;                                           \
            int _r = _f >> 2, _c = _f & 3;                                     \
            uint32_t _so = (sb) + _r * PITCH + _c * 16;                        \
            CP16(_so,              pA0 + (size_t)_r * Kdim + (kb) + _c * 8);   \
            CP16(_so + TILE_B,     pA1 + (size_t)_r * Kdim + (kb) + _c * 8);   \
            CP16(_so + 2 * TILE_B, pB  + (size_t)_r * Kdim + (kb) + _c * 8);   \
        }                                                                      \
        CP_COMMIT();                                                           \
    } while (0)

template <int PERM>
__global__ __launch_bounds__(256, 2) void hgemm(
    const h16* __restrict__ A0g, const h16* __restrict__ A1g,
    const h16* __restrict__ Bg,
    float* __restrict__ Cf, h16* __restrict__ C0, h16* __restrict__ C1)
{
    extern __shared__ char sm[];
    const int tid = threadIdx.x;
    const int lane = tid & 31;
    const int wid = tid >> 5;
    const int wm = wid & 1;       // 0..1 (64 rows)
    const int wn = wid >> 1;      // 0..3 (32 cols)
    const int brow = blockIdx.y * 128;
    const int bcol = blockIdx.x * 128;
    const uint32_t sbase = smem_u32(sm);

    const h16* pA0 = A0g + (size_t)brow * Kdim;
    const h16* pA1 = A1g + (size_t)brow * Kdim;
    const h16* pB  = Bg  + (size_t)bcol * Kdim;

    float acc[4][4][4];
#pragma unroll
    for (int i = 0; i < 4; i++)
#pragma unroll
        for (int j = 0; j < 4; j++)
#pragma unroll
            for (int q = 0; q < 4; q++) acc[i][j][q] = 0.f;

    const uint32_t a_off = (uint32_t)((wm * 64 + (lane & 15)) * PITCH + (lane >> 4) * 16);
    const uint32_t b_off = (uint32_t)((wn * 32 + (lane & 15)) * PITCH + (lane >> 4) * 16);

    LOAD_STAGE(sbase, 0);
    LOAD_STAGE(sbase + STAGE_B, 32);

    for (int it = 0; it < NIT; it++) {
        if (it < NIT - 1) CP_WAIT1(); else CP_WAIT0();
        __syncthreads();
        if (it + 2 < NIT) {
            int ns = (it + 2) % 3;
            LOAD_STAGE(sbase + ns * STAGE_B, (it + 2) * 32);
        }
        const uint32_t st = sbase + (it % 3) * STAGE_B;
#pragma unroll
        for (int ks = 0; ks < 2; ks++) {
            const uint32_t kso = ks * 32;
            uint32_t a0[4][4], a1[4][4], b[4][2];
#pragma unroll
            for (int mt = 0; mt < 4; mt++) {
                uint32_t ad = st + a_off + mt * 16 * PITCH + kso;
                LDSM_X4(a0[mt][0], a0[mt][1], a0[mt][2], a0[mt][3], ad);
                LDSM_X4(a1[mt][0], a1[mt][1], a1[mt][2], a1[mt][3], ad + TILE_B);
            }
            {
                uint32_t bd = st + 2 * TILE_B + b_off + kso;
                uint32_t r0, r1, r2, r3;
                LDSM_X4(r0, r1, r2, r3, bd);
                b[0][0] = r0; b[0][1] = r2;
                b[1][0] = r1; b[1][1] = r3;
                LDSM_X4(r0, r1, r2, r3, bd + 16 * PITCH);
                b[2][0] = r0; b[2][1] = r2;
                b[3][0] = r1; b[3][1] = r3;
            }
#pragma unroll
            for (int mt = 0; mt < 4; mt++)
#pragma unroll
                for (int nt = 0; nt < 4; nt++) {
                    MMA(acc[mt][nt], a0[mt], b[nt]);
                    MMA(acc[mt][nt], a1[mt], b[nt]);
                }
        }
    }

    // ---- epilogue ----
#pragma unroll
    for (int mt = 0; mt < 4; mt++) {
#pragma unroll
        for (int nt = 0; nt < 4; nt++) {
            int m = brow + wm * 64 + mt * 16 + (lane >> 2);
            int n = bcol + wn * 32 + nt * 8 + (lane & 3) * 2;
#pragma unroll
            for (int half = 0; half < 2; half++) {
                int mm = m + half * 8;
                float f0 = acc[mt][nt][2 * half];
                float f1 = acc[mt][nt][2 * half + 1];
                if (PERM) {
                    // mm = b*2048 + t ; n = h*64 + d
                    int bb = mm >> 11, t = mm & 2047, h = n >> 6;
                    int prow = (bb << 11) + (h << 7) + (t >> 4);
                    int pcol = ((t & 15) << 6) + (n & 63);
                    size_t idx = (size_t)prow * Ndim + pcol;
                    h16 h0 = __float2half_rn(f0), h1 = __float2half_rn(f1);
                    h16 l0 = __float2half_rn(f0 - __half2float(h0));
                    h16 l1 = __float2half_rn(f1 - __half2float(h1));
                    __half2 ph = __halves2half2(h0, h1);
                    __half2 pl = __halves2half2(l0, l1);
                    *(uint32_t*)(C0 + idx) = *(uint32_t*)&ph;
                    *(uint32_t*)(C1 + idx) = *(uint32_t*)&pl;
                } else {
                    *(float2*)(Cf + (size_t)mm * Ndim + n) = make_float2(f0, f1);
                }
            }
        }
    }
}

// ---------------------------------------------------------------------------
extern "C" void kernel_launch(void* const* d_in, const int* in_sizes, int n_in,
                              void* d_out, int out_size)
{
    const float *x, *Wv, *Wo;
    if (in_sizes[0] == Mdim * Kdim) {            // insertion order: x,mask,Wq,Wk,Wv,Wo
        x = (const float*)d_in[0];
        Wv = (const float*)d_in[4];
        Wo = (const float*)d_in[5];
    } else {                                      // alphabetical fallback
        x = (const float*)d_in[5];
        Wv = (const float*)d_in[3];
        Wo = (const float*)d_in[1];
    }
    float* out = (float*)d_out;

    h16 *x0, *x1, *wvT, *wo, *v0, *v1;
    cudaGetSymbolAddress((void**)&x0, g_x0);
    cudaGetSymbolAddress((void**)&x1, g_x1);
    cudaGetSymbolAddress((void**)&wvT, g_wvT);
    cudaGetSymbolAddress((void**)&wo, g_wo);
    cudaGetSymbolAddress((void**)&v0, g_v0);
    cudaGetSymbolAddress((void**)&v1, g_v1);

    cudaFuncSetAttribute(hgemm<1>, cudaFuncAttributeMaxDynamicSharedMemorySize, SMEM_DYN);
    cudaFuncSetAttribute(hgemm<0>, cudaFuncAttributeMaxDynamicSharedMemorySize, SMEM_DYN);

    split_x_kernel<<<(Mdim * Kdim / 4 + 255) / 256, 256>>>(x, x0, x1, Mdim * Kdim / 4);
    convT_kernel<<<dim3(Kdim / 32, Ndim / 32), dim3(32, 8)>>>(Wv, wvT);
    conv_kernel<<<(Ndim * Kdim / 4 + 255) / 256, 256>>>(Wo, wo, Ndim * Kdim / 4);

    dim3 grid(Ndim / 128, Mdim / 128);  // (8, 64)
    hgemm<1><<<grid, 256, SMEM_DYN>>>(x0, x1, wvT, nullptr, v0, v1);
    hgemm<0><<<grid, 256, SMEM_DYN>>>(v0, v1, wo, out, nullptr, nullptr);
}

// round 17
// speedup vs baseline: 5.4768x; 1.7002x over previous
#include <cuda_runtime.h>
#include <cuda_fp16.h>
#include <cstdint>

// out = perm(x @ Wv) @ Wo^T  (reference attention is numerically dead:
// softmax rows sum to 1, einsum 'bhtl,bthd->bhtd' contracts l over A alone).
//
// Single-fp16 HMMA (mma.sync m16n8k16). Calibrated error model: each fp16
// quantization term contributes ~2e-4 (measured 2.83e-4 with 2 terms);
// 4 terms (x, Wv, V, Wo) -> ~4e-4 total, 2.5x under the 1e-3 threshold.
// 4-stage cp.async ring, one barrier per K-iteration.

#define Mdim 8192
#define Ndim 1024
#define Kdim 1024
typedef __half h16;

// ---- device scratch (allocation-free rule) ----
__device__ h16 g_x[Mdim * Kdim];
__device__ h16 g_wvT[Ndim * Kdim];
__device__ h16 g_wo[Ndim * Kdim];
__device__ h16 g_v[Mdim * Kdim];

__device__ __forceinline__ uint32_t smem_u32(const void* p) {
    uint32_t a;
    asm("{ .reg .u64 t; cvta.to.shared.u64 t, %1; cvt.u32.u64 %0, t; }"
        : "=r"(a) : "l"(p));
    return a;
}

#define CP16(dst, src)                                                         \
    asm volatile("cp.async.cg.shared.global [%0], [%1], 16;" ::                \
                 "r"(dst), "l"(src))
#define CP_COMMIT() asm volatile("cp.async.commit_group;")
#define CP_WAIT2()  asm volatile("cp.async.wait_group 2;")
#define CP_WAIT1()  asm volatile("cp.async.wait_group 1;")
#define CP_WAIT0()  asm volatile("cp.async.wait_group 0;")

#define LDSM_X4(r0, r1, r2, r3, addr)                                          \
    asm volatile("ldmatrix.sync.aligned.m8n8.x4.shared.b16 {%0,%1,%2,%3}, [%4];" \
                 : "=r"(r0), "=r"(r1), "=r"(r2), "=r"(r3) : "r"(addr))

#define MMA(d, a, b)                                                           \
    asm volatile("mma.sync.aligned.m16n8k16.row.col.f32.f16.f16.f32 "          \
                 "{%0,%1,%2,%3}, {%4,%5,%6,%7}, {%8,%9}, {%0,%1,%2,%3};"       \
                 : "+f"((d)[0]), "+f"((d)[1]), "+f"((d)[2]), "+f"((d)[3])      \
                 : "r"((a)[0]), "r"((a)[1]), "r"((a)[2]), "r"((a)[3]),         \
                   "r"((b)[0]), "r"((b)[1]))

// ---------------- conversion kernels --------------------------------------
__global__ void conv_kernel(const float* __restrict__ in, h16* __restrict__ o, int n4)
{
    int i = blockIdx.x * blockDim.x + threadIdx.x;
    if (i >= n4) return;
    float4 v = ((const float4*)in)[i];
    __half2 a = __halves2half2(__float2half_rn(v.x), __float2half_rn(v.y));
    __half2 b = __halves2half2(__float2half_rn(v.z), __float2half_rn(v.w));
    ((uint2*)o)[i] = make_uint2(*(uint32_t*)&a, *(uint32_t*)&b);
}

// Wv [k][n] -> fp16 [n][k] via 32x32 smem tiles (coalesced both sides)
__global__ void convT_kernel(const float* __restrict__ in, h16* __restrict__ o)
{
    __shared__ float t[32][33];
    int k0 = blockIdx.x * 32, n0 = blockIdx.y * 32;
    int tx = threadIdx.x, ty = threadIdx.y;
    for (int j = ty; j < 32; j += 8)
        t[j][tx] = in[(size_t)(k0 + j) * Ndim + n0 + tx];
    __syncthreads();
    for (int j = ty; j < 32; j += 8)
        o[(size_t)(n0 + j) * Kdim + k0 + tx] = __float2half_rn(t[tx][j]);
}

// ---------------- fp16 HMMA GEMM -------------------------------------------
// Block 128x128, BK=32, 8 warps (2 M x 4 N), warp tile 64x32.
// D[m,n] = sum_k A[m,k]*B[n,k]; B [n][k] row-major == mma ".col" operand.
// 4-stage cp.async ring, ONE __syncthreads per iteration.
#define PITCH 80                     // padded row bytes (32 fp16 = 64B data)
#define TILE_B (128 * PITCH)         // 10240
#define STAGE_B (2 * TILE_B)         // 20480 (a, b)
#define NSTG 4
#define SMEM_DYN (NSTG * STAGE_B)    // 81920
#define NIT (Kdim / 32)              // 32

#define LOAD_STAGE(sb, kb)                                                     \
    do {                                                                       \
        _Pragma("unroll")                                                      \
        for (int _i = 0; _i < 2; _i++) {                                       \
            int _f = tid + _i * 256;                                           \
            int _r = _f >> 2, _c = _f & 3;                                     \
            uint32_t _so = (sb) + _r * PITCH + _c * 16;                        \
            CP16(_so,          pA + (size_t)_r * Kdim + (kb) + _c * 8);        \
            CP16(_so + TILE_B, pB + (size_t)_r * Kdim + (kb) + _c * 8);        \
        }                                                                      \
        CP_COMMIT();                                                           \
    } while (0)

template <int PERM>
__global__ __launch_bounds__(256, 2) void hgemm(
    const h16* __restrict__ Ag, const h16* __restrict__ Bg,
    float* __restrict__ Cf, h16* __restrict__ Ch)
{
    extern __shared__ char sm[];
    const int tid = threadIdx.x;
    const int lane = tid & 31;
    const int wid = tid >> 5;
    const int wm = wid & 1;       // 0..1 (64 rows)
    const int wn = wid >> 1;      // 0..3 (32 cols)
    const int brow = blockIdx.y * 128;
    const int bcol = blockIdx.x * 128;
    const uint32_t sbase = smem_u32(sm);

    const h16* pA = Ag + (size_t)brow * Kdim;
    const h16* pB = Bg + (size_t)bcol * Kdim;

    float acc[4][4][4];
#pragma unroll
    for (int i = 0; i < 4; i++)
#pragma unroll
        for (int j = 0; j < 4; j++)
#pragma unroll
            for (int q = 0; q < 4; q++) acc[i][j][q] = 0.f;

    const uint32_t a_off = (uint32_t)((wm * 64 + (lane & 15)) * PITCH + (lane >> 4) * 16);
    const uint32_t b_off = (uint32_t)((wn * 32 + (lane & 15)) * PITCH + (lane >> 4) * 16);

    LOAD_STAGE(sbase, 0);
    LOAD_STAGE(sbase + STAGE_B, 32);
    LOAD_STAGE(sbase + 2 * STAGE_B, 64);

    for (int it = 0; it < NIT; it++) {
        if (it < NIT - 2) CP_WAIT2();
        else if (it == NIT - 2) CP_WAIT1();
        else CP_WAIT0();
        __syncthreads();
        if (it + 3 < NIT) {
            int ns = (it + 3) & (NSTG - 1);
            LOAD_STAGE(sbase + ns * STAGE_B, (it + 3) * 32);
        }
        const uint32_t st = sbase + (it & (NSTG - 1)) * STAGE_B;
#pragma unroll
        for (int ks = 0; ks < 2; ks++) {
            const uint32_t kso = ks * 32;
            uint32_t a[4][4], b[4][2];
#pragma unroll
            for (int mt = 0; mt < 4; mt++) {
                uint32_t ad = st + a_off + mt * 16 * PITCH + kso;
                LDSM_X4(a[mt][0], a[mt][1], a[mt][2], a[mt][3], ad);
            }
            {
                uint32_t bd = st + TILE_B + b_off + kso;
                uint32_t r0, r1, r2, r3;
                LDSM_X4(r0, r1, r2, r3, bd);
                b[0][0] = r0; b[0][1] = r2;
                b[1][0] = r1; b[1][1] = r3;
                LDSM_X4(r0, r1, r2, r3, bd + 16 * PITCH);
                b[2][0] = r0; b[2][1] = r2;
                b[3][0] = r1; b[3][1] = r3;
            }
#pragma unroll
            for (int mt = 0; mt < 4; mt++)
#pragma unroll
                for (int nt = 0; nt < 4; nt++)
                    MMA(acc[mt][nt], a[mt], b[nt]);
        }
    }

    // ---- epilogue ----
#pragma unroll
    for (int mt = 0; mt < 4; mt++) {
#pragma unroll
        for (int nt = 0; nt < 4; nt++) {
            int m = brow + wm * 64 + mt * 16 + (lane >> 2);
            int n = bcol + wn * 32 + nt * 8 + (lane & 3) * 2;
#pragma unroll
            for (int half = 0; half < 2; half++) {
                int mm = m + half * 8;
                float f0 = acc[mt][nt][2 * half];
                float f1 = acc[mt][nt][2 * half + 1];
                if (PERM) {
                    // mm = b*2048 + t ; n = h*64 + d
                    int bb = mm >> 11, t = mm & 2047, h = n >> 6;
                    int prow = (bb << 11) + (h << 7) + (t >> 4);
                    int pcol = ((t & 15) << 6) + (n & 63);
                    size_t idx = (size_t)prow * Ndim + pcol;
                    __half2 ph = __halves2half2(__float2half_rn(f0),
                                                __float2half_rn(f1));
                    *(uint32_t*)(Ch + idx) = *(uint32_t*)&ph;
                } else {
                    *(float2*)(Cf + (size_t)mm * Ndim + n) = make_float2(f0, f1);
                }
            }
        }
    }
}

// ---------------------------------------------------------------------------
extern "C" void kernel_launch(void* const* d_in, const int* in_sizes, int n_in,
                              void* d_out, int out_size)
{
    const float *x, *Wv, *Wo;
    if (in_sizes[0] == Mdim * Kdim) {            // insertion order: x,mask,Wq,Wk,Wv,Wo
        x = (const float*)d_in[0];
        Wv = (const float*)d_in[4];
        Wo = (const float*)d_in[5];
    } else {                                      // alphabetical fallback
        x = (const float*)d_in[5];
        Wv = (const float*)d_in[3];
        Wo = (const float*)d_in[1];
    }
    float* out = (float*)d_out;

    h16 *xh, *wvT, *wo, *v;
    cudaGetSymbolAddress((void**)&xh, g_x);
    cudaGetSymbolAddress((void**)&wvT, g_wvT);
    cudaGetSymbolAddress((void**)&wo, g_wo);
    cudaGetSymbolAddress((void**)&v, g_v);

    cudaFuncSetAttribute(hgemm<1>, cudaFuncAttributeMaxDynamicSharedMemorySize, SMEM_DYN);
    cudaFuncSetAttribute(hgemm<0>, cudaFuncAttributeMaxDynamicSharedMemorySize, SMEM_DYN);

    conv_kernel<<<(Mdim * Kdim / 4 + 255) / 256, 256>>>(x, xh, Mdim * Kdim / 4);
    convT_kernel<<<dim3(Kdim / 32, Ndim / 32), dim3(32, 8)>>>(Wv, wvT);
    conv_kernel<<<(Ndim * Kdim / 4 + 255) / 256, 256>>>(Wo, wo, Ndim * Kdim / 4);

    dim3 grid(Ndim / 128, Mdim / 128);  // (8, 64)
    hgemm<1><<<grid, 256, SMEM_DYN>>>(xh, wvT, nullptr, v);
    hgemm<0><<<grid, 256, SMEM_DYN>>>(v, wo, out, nullptr);
}